// round 9
// baseline (speedup 1.0000x reference)
#include <cuda_runtime.h>
#include <math.h>

#define CEn 128
#define TCn 1024
#define NWn 64
#define Wn  16
#define Tn  65536
#define Bn  4
#define EPSn 1e-5f
#define SLOPEn 0.01f

typedef unsigned long long ull;

__device__ __forceinline__ ull pk2(float lo, float hi) {
    ull r; asm("mov.b64 %0, {%1, %2};" : "=l"(r) : "f"(lo), "f"(hi)); return r;
}
__device__ __forceinline__ void upk2(float& lo, float& hi, ull v) {
    asm("mov.b64 {%0, %1}, %2;" : "=f"(lo), "=f"(hi) : "l"(v));
}
__device__ __forceinline__ ull fma2(ull a, ull b, ull c) {
    ull r; asm("fma.rn.f32x2 %0, %1, %2, %3;" : "=l"(r) : "l"(a), "l"(b), "l"(c)); return r;
}

// Intermediate FiLM params: [B][4*NW][TC] = 4 MB
__device__ float g_film[Bn * 4 * NWn * TCn];

// ---------------------------------------------------------------------------
// Kernel 1: TimeDistributedMLP, tiled 16 time-columns per block.
// ---------------------------------------------------------------------------
#define TT 16
__global__ void __launch_bounds__(128)
mlp_kernel(const float* __restrict__ ce,
           const float* __restrict__ w0, const float* __restrict__ b0,
           const float* __restrict__ g0, const float* __restrict__ e0,
           const float* __restrict__ w1, const float* __restrict__ b1,
           const float* __restrict__ g1, const float* __restrict__ e1,
           const float* __restrict__ w2, const float* __restrict__ b2,
           const float* __restrict__ g2, const float* __restrict__ e2,
           const float* __restrict__ w3, const float* __restrict__ b3)
{
    __shared__ float xs[TT][CEn];
    __shared__ float red1[TT][4], red2[TT][4];

    const int t0  = blockIdx.x * TT;
    const int b   = blockIdx.y;
    const int tid = threadIdx.x;
    const int lane = tid & 31;
    const int wid  = tid >> 5;

#pragma unroll
    for (int tt = 0; tt < TT; tt++)
        xs[tt][tid] = ce[(b * CEn + tid) * TCn + t0 + tt];
    __syncthreads();

    const float* Ws[3] = { w0, w1, w2 };
    const float* Bs[3] = { b0, b1, b2 };
    const float* Gs[3] = { g0, g1, g2 };
    const float* Es[3] = { e0, e1, e2 };

    float acc[TT];

    for (int l = 0; l < 3; l++) {
        const float bb = Bs[l][tid];
#pragma unroll
        for (int tt = 0; tt < TT; tt++) acc[tt] = bb;

        const float4* wr = (const float4*)(Ws[l] + tid * CEn);
        for (int i = 0; i < CEn / 4; i++) {
            float4 wv = wr[i];
#pragma unroll
            for (int tt = 0; tt < TT; tt++) {
                const float4 xv = *(const float4*)&xs[tt][4 * i];
                acc[tt] += xv.x * wv.x + xv.y * wv.y + xv.z * wv.z + xv.w * wv.w;
            }
        }

#pragma unroll
        for (int tt = 0; tt < TT; tt++) {
            float s1 = acc[tt], s2 = acc[tt] * acc[tt];
#pragma unroll
            for (int o = 16; o > 0; o >>= 1) {
                s1 += __shfl_xor_sync(0xffffffffu, s1, o);
                s2 += __shfl_xor_sync(0xffffffffu, s2, o);
            }
            if (lane == 0) { red1[tt][wid] = s1; red2[tt][wid] = s2; }
        }
        __syncthreads();

        const float gg = Gs[l][tid], ee = Es[l][tid];
#pragma unroll
        for (int tt = 0; tt < TT; tt++) {
            float s1 = red1[tt][0] + red1[tt][1] + red1[tt][2] + red1[tt][3];
            float s2 = red2[tt][0] + red2[tt][1] + red2[tt][2] + red2[tt][3];
            float mu  = s1 * (1.0f / CEn);
            float var = s2 * (1.0f / CEn) - mu * mu;
            float v = (acc[tt] - mu) * rsqrtf(var + EPSn);
            v = v * gg + ee;
            acc[tt] = (v > 0.0f) ? v : SLOPEn * v;
        }
        __syncthreads();
#pragma unroll
        for (int tt = 0; tt < TT; tt++) xs[tt][tid] = acc[tt];
        __syncthreads();
    }

#pragma unroll
    for (int r = 0; r < 2; r++) {
        const int o = tid + r * CEn;
        const float bb = b3[o];
        float a2[TT];
#pragma unroll
        for (int tt = 0; tt < TT; tt++) a2[tt] = bb;
        const float4* wr = (const float4*)(w3 + o * CEn);
        for (int i = 0; i < CEn / 4; i++) {
            float4 wv = wr[i];
#pragma unroll
            for (int tt = 0; tt < TT; tt++) {
                const float4 xv = *(const float4*)&xs[tt][4 * i];
                a2[tt] += xv.x * wv.x + xv.y * wv.y + xv.z * wv.z + xv.w * wv.w;
            }
        }
#pragma unroll
        for (int tt = 0; tt < TT; tt++)
            g_film[(b * 4 * NWn + o) * TCn + t0 + tt] = a2[tt];
    }
}

// ---------------------------------------------------------------------------
// Kernel 2: fused waveshaper with packed f32x2 math along the W dimension.
// 256 threads * 2 samples = 512 samples/block.
// ---------------------------------------------------------------------------
#define S_SW1   0                    // [64][16][16]
#define S_SW0   16384                // [64][16]
#define S_SB0   17408
#define S_SB1   18432
#define S_SW2   19456
#define S_SB2   20480
#define S_ISC   20544
#define S_MIXW  20608
#define S_FILM  20672                // [4][64][10]
#define S_TOTAL (20672 + 4 * 64 * 10)
#define NFRAMES 10

__global__ void __launch_bounds__(256, 2)
newt_kernel(const float* __restrict__ exciter,
            const float* __restrict__ iscale,
            const float* __restrict__ sw0, const float* __restrict__ sb0,
            const float* __restrict__ sw1, const float* __restrict__ sb1,
            const float* __restrict__ sw2, const float* __restrict__ sb2,
            const float* __restrict__ mixw, const float* __restrict__ mixb,
            float* __restrict__ out)
{
    extern __shared__ float sm[];

    const int tid = threadIdx.x;
    const int b   = blockIdx.y;
    const int t0  = blockIdx.x * 512;
    const int ta  = t0 + 2 * tid;

    // ---- stage weights ----
    for (int i = tid; i < 16384 / 4; i += 256)
        ((float4*)(sm + S_SW1))[i] = ((const float4*)sw1)[i];
    for (int i = tid; i < 1024 / 4; i += 256) {
        ((float4*)(sm + S_SW0))[i] = ((const float4*)sw0)[i];
        ((float4*)(sm + S_SB0))[i] = ((const float4*)sb0)[i];
        ((float4*)(sm + S_SB1))[i] = ((const float4*)sb1)[i];
        ((float4*)(sm + S_SW2))[i] = ((const float4*)sw2)[i];
    }
    if (tid < 64) {
        sm[S_SB2 + tid]  = sb2[tid];
        sm[S_ISC + tid]  = iscale[tid];
        sm[S_MIXW + tid] = mixw[tid];
    }

    // ---- stage film frame window ----
    int base = (int)floorf((t0 + 0.5f) * (1.0f / 64.0f) - 0.5f);
    if (base < 0) base = 0;
    const float* filmB = g_film + b * (4 * NWn * TCn);
    for (int idx = tid; idx < 4 * NWn * NFRAMES; idx += 256) {
        const int p = idx / (NWn * NFRAMES);
        const int rem = idx - p * (NWn * NFRAMES);
        const int c = rem / NFRAMES;
        const int f = rem - c * NFRAMES;
        int fr = base + f; if (fr > TCn - 1) fr = TCn - 1;
        sm[S_FILM + (p * NWn + c) * NFRAMES + f] = filmB[(p * NWn + c) * TCn + fr];
    }
    __syncthreads();

    float pos = (ta + 0.5f) * (1.0f / 64.0f) - 0.5f;
    pos = fminf(fmaxf(pos, 0.0f), (float)(TCn - 1));
    int i0a = (int)pos;
    int i1a = min(i0a + 1, TCn - 1);
    const float fra = pos - (float)i0a;
    i0a -= base; i1a -= base;

    pos = (ta + 1.5f) * (1.0f / 64.0f) - 0.5f;
    pos = fminf(fmaxf(pos, 0.0f), (float)(TCn - 1));
    int i0b = (int)pos;
    int i1b = min(i0b + 1, TCn - 1);
    const float frb = pos - (float)i0b;
    i0b -= base; i1b -= base;

    float acc0 = 0.0f, acc1 = 0.0f;

    for (int c = 0; c < NWn; c++) {
        const float* fgi = sm + S_FILM + (0 * NWn + c) * NFRAMES;
        const float* fbi = sm + S_FILM + (1 * NWn + c) * NFRAMES;
        const float* fgn = sm + S_FILM + (2 * NWn + c) * NFRAMES;
        const float* fbn = sm + S_FILM + (3 * NWn + c) * NFRAMES;

        const float gia = fgi[i0a] + (fgi[i1a] - fgi[i0a]) * fra;
        const float gib = fgi[i0b] + (fgi[i1b] - fgi[i0b]) * frb;
        const float bia = fbi[i0a] + (fbi[i1a] - fbi[i0a]) * fra;
        const float bib = fbi[i0b] + (fbi[i1b] - fbi[i0b]) * frb;
        const float gna = fgn[i0a] + (fgn[i1a] - fgn[i0a]) * fra;
        const float gnb = fgn[i0b] + (fgn[i1b] - fgn[i0b]) * frb;
        const float bna = fbn[i0a] + (fbn[i1a] - fbn[i0a]) * fra;
        const float bnb = fbn[i0b] + (fbn[i1b] - fbn[i0b]) * frb;

        const float2 e = __ldg(((const float2*)(exciter + (b * NWn + c) * Tn)) + (t0 >> 1) + tid);
        const float isc = sm[S_ISC + c];

        const float x0 = isc * (gia * e.x + bia);
        const float x1 = isc * (gib * e.y + bib);

        // layer 0: 1 -> 16, sine. Packed along W (weight pairs contiguous).
        ull h0a[Wn / 2], h0b[Wn / 2];             // packed (w-pair) activations
        {
            const ull xp0 = pk2(x0, x0);
            const ull xp1 = pk2(x1, x1);
            const ulonglong2* w0v = (const ulonglong2*)(sm + S_SW0 + c * Wn);
            const ulonglong2* b0v = (const ulonglong2*)(sm + S_SB0 + c * Wn);
#pragma unroll
            for (int j = 0; j < Wn / 4; j++) {
                const ulonglong2 w  = w0v[j];
                const ulonglong2 bb = b0v[j];
                ull p0 = fma2(xp0, w.x, bb.x);
                ull p1 = fma2(xp0, w.y, bb.y);
                ull q0 = fma2(xp1, w.x, bb.x);
                ull q1 = fma2(xp1, w.y, bb.y);
                float l, h;
                upk2(l, h, p0); h0a[2*j+0] = pk2(__sinf(l), __sinf(h));
                upk2(l, h, p1); h0a[2*j+1] = pk2(__sinf(l), __sinf(h));
                upk2(l, h, q0); h0b[2*j+0] = pk2(__sinf(l), __sinf(h));
                upk2(l, h, q1); h0b[2*j+1] = pk2(__sinf(l), __sinf(h));
            }
        }

        // layer 1: 16 -> 16, sine. Dot product via packed pairs.
        ull h1a[Wn / 2], h1b[Wn / 2];
        const float* b1s = sm + S_SB1 + c * Wn;
#pragma unroll
        for (int op = 0; op < Wn / 2; op++) {     // output pairs
            float so[2][2];                        // [out-in-pair][sample]
#pragma unroll
            for (int oo = 0; oo < 2; oo++) {
                const int o = 2 * op + oo;
                ull a0 = 0ull, a1 = 0ull;
                const ulonglong2* wv = (const ulonglong2*)(sm + S_SW1 + (c * Wn + o) * Wn);
#pragma unroll
                for (int i = 0; i < Wn / 4; i++) {
                    const ulonglong2 w = wv[i];
                    a0 = fma2(h0a[2*i+0], w.x, a0);
                    a0 = fma2(h0a[2*i+1], w.y, a0);
                    a1 = fma2(h0b[2*i+0], w.x, a1);
                    a1 = fma2(h0b[2*i+1], w.y, a1);
                }
                const float bb = b1s[o];
                float l, h;
                upk2(l, h, a0); so[oo][0] = __sinf(l + h + bb);
                upk2(l, h, a1); so[oo][1] = __sinf(l + h + bb);
            }
            h1a[op] = pk2(so[0][0], so[1][0]);
            h1b[op] = pk2(so[0][1], so[1][1]);
        }

        // layer 2: 16 -> 1, sine
        {
            ull a0 = 0ull, a1 = 0ull;
            const ulonglong2* w2v = (const ulonglong2*)(sm + S_SW2 + c * Wn);
#pragma unroll
            for (int i = 0; i < Wn / 4; i++) {
                const ulonglong2 w = w2v[i];
                a0 = fma2(h1a[2*i+0], w.x, a0);
                a0 = fma2(h1a[2*i+1], w.y, a0);
                a1 = fma2(h1b[2*i+0], w.x, a1);
                a1 = fma2(h1b[2*i+1], w.y, a1);
            }
            const float bb = sm[S_SB2 + c];
            float l, h;
            upk2(l, h, a0); const float y0 = __sinf(l + h + bb);
            upk2(l, h, a1); const float y1 = __sinf(l + h + bb);

            const float mw = sm[S_MIXW + c];
            acc0 += mw * (gna * y0 + bna);
            acc1 += mw * (gnb * y1 + bnb);
        }
    }

    const float mb = __ldg(mixb);
    const float o0 = acc0 + mb;
    const float o1 = acc1 + mb;

    float4* o4 = (float4*)out;
    o4[b * Tn + ta + 0] = make_float4(o0, o0, o0, o0);
    o4[b * Tn + ta + 1] = make_float4(o1, o1, o1, o1);
}

// ---------------------------------------------------------------------------
extern "C" void kernel_launch(void* const* d_in, const int* in_sizes, int n_in,
                              void* d_out, int out_size)
{
    const float* exciter = (const float*)d_in[0];
    const float* cemb    = (const float*)d_in[1];
    const float* mlp_w0  = (const float*)d_in[2];
    const float* mlp_b0  = (const float*)d_in[3];
    const float* ln0_g   = (const float*)d_in[4];
    const float* ln0_b   = (const float*)d_in[5];
    const float* mlp_w1  = (const float*)d_in[6];
    const float* mlp_b1  = (const float*)d_in[7];
    const float* ln1_g   = (const float*)d_in[8];
    const float* ln1_b   = (const float*)d_in[9];
    const float* mlp_w2  = (const float*)d_in[10];
    const float* mlp_b2  = (const float*)d_in[11];
    const float* ln2_g   = (const float*)d_in[12];
    const float* ln2_b   = (const float*)d_in[13];
    const float* mlp_w3  = (const float*)d_in[14];
    const float* mlp_b3  = (const float*)d_in[15];
    const float* iscale  = (const float*)d_in[16];
    const float* sf_w0   = (const float*)d_in[17];
    const float* sf_b0   = (const float*)d_in[18];
    const float* sf_w1   = (const float*)d_in[19];
    const float* sf_b1   = (const float*)d_in[20];
    const float* sf_w2   = (const float*)d_in[21];
    const float* sf_b2   = (const float*)d_in[22];
    const float* mix_w   = (const float*)d_in[23];
    const float* mix_b   = (const float*)d_in[24];
    float* out = (float*)d_out;

    dim3 g1(TCn / TT, Bn);
    mlp_kernel<<<g1, CEn>>>(cemb,
                            mlp_w0, mlp_b0, ln0_g, ln0_b,
                            mlp_w1, mlp_b1, ln1_g, ln1_b,
                            mlp_w2, mlp_b2, ln2_g, ln2_b,
                            mlp_w3, mlp_b3);

    const int smem_bytes = S_TOTAL * 4;
    cudaFuncSetAttribute(newt_kernel, cudaFuncAttributeMaxDynamicSharedMemorySize, smem_bytes);
    dim3 g2(Tn / 512, Bn);
    newt_kernel<<<g2, 256, smem_bytes>>>(exciter, iscale,
                                         sf_w0, sf_b0, sf_w1, sf_b1, sf_w2, sf_b2,
                                         mix_w, mix_b, out);
}

// round 10
// speedup vs baseline: 1.5608x; 1.5608x over previous
#include <cuda_runtime.h>
#include <math.h>

#define CEn 128
#define TCn 1024
#define NWn 64
#define Wn  16
#define Tn  65536
#define Bn  4
#define EPSn 1e-5f
#define SLOPEn 0.01f
#define TAB_N 32768

// FiLM params: [B][4*NW][TC] = 4 MB
__device__ float g_film[Bn * 4 * NWn * TCn];
// per-channel range inputs
__device__ unsigned int g_emax_bits[NWn];
__device__ float g_gimax[NWn];
__device__ float g_bimax[NWn];
// waveshaper table: per channel TAB_N+1 nodes of (f, h*f')
__device__ float2 g_tab[NWn * (TAB_N + 2)];

// ---------------------------------------------------------------------------
__device__ __forceinline__ float blockmax(float v, float* red) {
    const int lane = threadIdx.x & 31, wid = threadIdx.x >> 5;
#pragma unroll
    for (int o = 16; o > 0; o >>= 1)
        v = fmaxf(v, __shfl_xor_sync(0xffffffffu, v, o));
    if (lane == 0) red[wid] = v;
    __syncthreads();
    v = red[0];
#pragma unroll
    for (int w = 1; w < 8; w++) v = fmaxf(v, red[w]);
    return v;
}

__device__ __forceinline__ void get_range(int c, const float* __restrict__ iscale,
                                          float& x0, float& h) {
    const float em = __uint_as_float(g_emax_bits[c]);
    float xm = fabsf(iscale[c]) * (g_gimax[c] * em + g_bimax[c]);
    xm = xm * 1.0005f + 1e-5f;
    x0 = -xm;
    h  = (2.0f * xm) / (float)TAB_N;
}

// ---------------------------------------------------------------------------
__global__ void zero_kernel() {
    if (threadIdx.x < NWn) g_emax_bits[threadIdx.x] = 0u;
}

// max |exciter| per channel. grid (NW, 16), block 256.
__global__ void emax_kernel(const float* __restrict__ exciter) {
    __shared__ float red[8];
    const int c = blockIdx.x, s = blockIdx.y;
    float v = 0.0f;
    for (int b = 0; b < Bn; b++) {
        const float4* p = (const float4*)(exciter + (b * NWn + c) * Tn) + s * 1024;
#pragma unroll 4
        for (int i = threadIdx.x; i < 1024; i += 256) {
            float4 e = __ldg(p + i);
            v = fmaxf(v, fmaxf(fmaxf(fabsf(e.x), fabsf(e.y)),
                               fmaxf(fabsf(e.z), fabsf(e.w))));
        }
    }
    v = blockmax(v, red);
    if (threadIdx.x == 0)
        atomicMax(&g_emax_bits[c], __float_as_uint(v));
}

// max |gamma_i| (part 0) and |beta_i| (part 1) per channel. grid (NW, 2), block 256.
__global__ void filmmax_kernel() {
    __shared__ float red[8];
    const int c = blockIdx.x, p = blockIdx.y;
    float v = 0.0f;
    for (int b = 0; b < Bn; b++) {
        const float4* row = (const float4*)(g_film + (b * 4 * NWn + p * NWn + c) * TCn);
        for (int i = threadIdx.x; i < TCn / 4; i += 256) {
            float4 e = row[i];
            v = fmaxf(v, fmaxf(fmaxf(fabsf(e.x), fabsf(e.y)),
                               fmaxf(fabsf(e.z), fabsf(e.w))));
        }
    }
    v = blockmax(v, red);
    if (threadIdx.x == 0) {
        if (p == 0) g_gimax[c] = v; else g_bimax[c] = v;
    }
}

// ---------------------------------------------------------------------------
// Table build: f_c(x) and analytic derivative. grid ((TAB_N+1+255)/256, NW).
// ---------------------------------------------------------------------------
__global__ void __launch_bounds__(256)
build_kernel(const float* __restrict__ iscale,
             const float* __restrict__ sw0, const float* __restrict__ sb0,
             const float* __restrict__ sw1, const float* __restrict__ sb1,
             const float* __restrict__ sw2, const float* __restrict__ sb2)
{
    __shared__ float w0s[Wn], b0s[Wn], w1s[Wn * Wn], b1s[Wn], w2s[Wn];
    __shared__ float b2s;
    const int c = blockIdx.y;
    const int tid = threadIdx.x;
    if (tid < Wn) {
        w0s[tid] = sw0[c * Wn + tid];
        b0s[tid] = sb0[c * Wn + tid];
        b1s[tid] = sb1[c * Wn + tid];
        w2s[tid] = sw2[c * Wn + tid];
        if (tid == 0) b2s = sb2[c];
    }
    if (tid < Wn * Wn) w1s[tid] = sw1[c * Wn * Wn + tid];
    __syncthreads();

    const int k = blockIdx.x * 256 + tid;
    if (k > TAB_N) return;

    float x0, h;
    get_range(c, iscale, x0, h);
    const float x = fmaf((float)k, h, x0);

    float h0[Wn], d0[Wn];
#pragma unroll
    for (int j = 0; j < Wn; j++) {
        float s, cc;
        __sincosf(fmaf(x, w0s[j], b0s[j]), &s, &cc);
        h0[j] = s;
        d0[j] = w0s[j] * cc;
    }
    float h1[Wn], d1[Wn];
#pragma unroll
    for (int o = 0; o < Wn; o++) {
        float a = b1s[o], da = 0.0f;
#pragma unroll
        for (int j = 0; j < Wn; j++) {
            const float w = w1s[o * Wn + j];
            a  = fmaf(w, h0[j], a);
            da = fmaf(w, d0[j], da);
        }
        float s, cc;
        __sincosf(a, &s, &cc);
        h1[o] = s;
        d1[o] = cc * da;
    }
    float a = b2s, da = 0.0f;
#pragma unroll
    for (int o = 0; o < Wn; o++) {
        a  = fmaf(w2s[o], h1[o], a);
        da = fmaf(w2s[o], d1[o], da);
    }
    float s, cc;
    __sincosf(a, &s, &cc);
    g_tab[c * (TAB_N + 2) + k] = make_float2(s, h * cc * da);
}

// ---------------------------------------------------------------------------
// Kernel 1: TimeDistributedMLP, tiled 16 time-columns per block. (unchanged)
// ---------------------------------------------------------------------------
#define TT 16
__global__ void __launch_bounds__(128)
mlp_kernel(const float* __restrict__ ce,
           const float* __restrict__ w0, const float* __restrict__ b0,
           const float* __restrict__ g0, const float* __restrict__ e0,
           const float* __restrict__ w1, const float* __restrict__ b1,
           const float* __restrict__ g1, const float* __restrict__ e1,
           const float* __restrict__ w2, const float* __restrict__ b2,
           const float* __restrict__ g2, const float* __restrict__ e2,
           const float* __restrict__ w3, const float* __restrict__ b3)
{
    __shared__ float xs[TT][CEn];
    __shared__ float red1[TT][4], red2[TT][4];

    const int t0  = blockIdx.x * TT;
    const int b   = blockIdx.y;
    const int tid = threadIdx.x;
    const int lane = tid & 31;
    const int wid  = tid >> 5;

#pragma unroll
    for (int tt = 0; tt < TT; tt++)
        xs[tt][tid] = ce[(b * CEn + tid) * TCn + t0 + tt];
    __syncthreads();

    const float* Ws[3] = { w0, w1, w2 };
    const float* Bs[3] = { b0, b1, b2 };
    const float* Gs[3] = { g0, g1, g2 };
    const float* Es[3] = { e0, e1, e2 };

    float acc[TT];

    for (int l = 0; l < 3; l++) {
        const float bb = Bs[l][tid];
#pragma unroll
        for (int tt = 0; tt < TT; tt++) acc[tt] = bb;

        const float4* wr = (const float4*)(Ws[l] + tid * CEn);
        for (int i = 0; i < CEn / 4; i++) {
            float4 wv = wr[i];
#pragma unroll
            for (int tt = 0; tt < TT; tt++) {
                const float4 xv = *(const float4*)&xs[tt][4 * i];
                acc[tt] += xv.x * wv.x + xv.y * wv.y + xv.z * wv.z + xv.w * wv.w;
            }
        }

#pragma unroll
        for (int tt = 0; tt < TT; tt++) {
            float s1 = acc[tt], s2 = acc[tt] * acc[tt];
#pragma unroll
            for (int o = 16; o > 0; o >>= 1) {
                s1 += __shfl_xor_sync(0xffffffffu, s1, o);
                s2 += __shfl_xor_sync(0xffffffffu, s2, o);
            }
            if (lane == 0) { red1[tt][wid] = s1; red2[tt][wid] = s2; }
        }
        __syncthreads();

        const float gg = Gs[l][tid], ee = Es[l][tid];
#pragma unroll
        for (int tt = 0; tt < TT; tt++) {
            float s1 = red1[tt][0] + red1[tt][1] + red1[tt][2] + red1[tt][3];
            float s2 = red2[tt][0] + red2[tt][1] + red2[tt][2] + red2[tt][3];
            float mu  = s1 * (1.0f / CEn);
            float var = s2 * (1.0f / CEn) - mu * mu;
            float v = (acc[tt] - mu) * rsqrtf(var + EPSn);
            v = v * gg + ee;
            acc[tt] = (v > 0.0f) ? v : SLOPEn * v;
        }
        __syncthreads();
#pragma unroll
        for (int tt = 0; tt < TT; tt++) xs[tt][tid] = acc[tt];
        __syncthreads();
    }

#pragma unroll
    for (int r = 0; r < 2; r++) {
        const int o = tid + r * CEn;
        const float bb = b3[o];
        float a2[TT];
#pragma unroll
        for (int tt = 0; tt < TT; tt++) a2[tt] = bb;
        const float4* wr = (const float4*)(w3 + o * CEn);
        for (int i = 0; i < CEn / 4; i++) {
            float4 wv = wr[i];
#pragma unroll
            for (int tt = 0; tt < TT; tt++) {
                const float4 xv = *(const float4*)&xs[tt][4 * i];
                a2[tt] += xv.x * wv.x + xv.y * wv.y + xv.z * wv.z + xv.w * wv.w;
            }
        }
#pragma unroll
        for (int tt = 0; tt < TT; tt++)
            g_film[(b * 4 * NWn + o) * TCn + t0 + tt] = a2[tt];
    }
}

// ---------------------------------------------------------------------------
// Kernel 2: table-based waveshaper. 256 threads * 2 samples = 512 samples/block.
// ---------------------------------------------------------------------------
#define NFRAMES 10

__global__ void __launch_bounds__(256)
newt_kernel(const float* __restrict__ exciter,
            const float* __restrict__ iscale,
            const float* __restrict__ mixw, const float* __restrict__ mixb,
            float* __restrict__ out)
{
    __shared__ float smf[4 * NWn * NFRAMES];
    __shared__ float sm_isc[NWn], sm_mixw[NWn];
    __shared__ float sm_x0[NWn], sm_h[NWn], sm_invh[NWn];

    const int tid = threadIdx.x;
    const int b   = blockIdx.y;
    const int t0  = blockIdx.x * 512;
    const int ta  = t0 + 2 * tid;

    if (tid < NWn) {
        sm_isc[tid]  = iscale[tid];
        sm_mixw[tid] = mixw[tid];
        float x0, h;
        get_range(tid, iscale, x0, h);
        sm_x0[tid] = x0; sm_h[tid] = h; sm_invh[tid] = 1.0f / h;
    }

    int base = (int)floorf((t0 + 0.5f) * (1.0f / 64.0f) - 0.5f);
    if (base < 0) base = 0;
    const float* filmB = g_film + b * (4 * NWn * TCn);
    for (int idx = tid; idx < 4 * NWn * NFRAMES; idx += 256) {
        const int p = idx / (NWn * NFRAMES);
        const int rem = idx - p * (NWn * NFRAMES);
        const int c = rem / NFRAMES;
        const int f = rem - c * NFRAMES;
        int fr = base + f; if (fr > TCn - 1) fr = TCn - 1;
        smf[(p * NWn + c) * NFRAMES + f] = filmB[(p * NWn + c) * TCn + fr];
    }
    __syncthreads();

    float pos = (ta + 0.5f) * (1.0f / 64.0f) - 0.5f;
    pos = fminf(fmaxf(pos, 0.0f), (float)(TCn - 1));
    int i0a = (int)pos;
    int i1a = min(i0a + 1, TCn - 1);
    const float fra = pos - (float)i0a;
    i0a -= base; i1a -= base;

    pos = (ta + 1.5f) * (1.0f / 64.0f) - 0.5f;
    pos = fminf(fmaxf(pos, 0.0f), (float)(TCn - 1));
    int i0b = (int)pos;
    int i1b = min(i0b + 1, TCn - 1);
    const float frb = pos - (float)i0b;
    i0b -= base; i1b -= base;

    float acc0 = 0.0f, acc1 = 0.0f;

#pragma unroll 2
    for (int c = 0; c < NWn; c++) {
        const float* fgi = smf + (0 * NWn + c) * NFRAMES;
        const float* fbi = smf + (1 * NWn + c) * NFRAMES;
        const float* fgn = smf + (2 * NWn + c) * NFRAMES;
        const float* fbn = smf + (3 * NWn + c) * NFRAMES;

        const float gia = fgi[i0a] + (fgi[i1a] - fgi[i0a]) * fra;
        const float gib = fgi[i0b] + (fgi[i1b] - fgi[i0b]) * frb;
        const float bia = fbi[i0a] + (fbi[i1a] - fbi[i0a]) * fra;
        const float bib = fbi[i0b] + (fbi[i1b] - fbi[i0b]) * frb;
        const float gna = fgn[i0a] + (fgn[i1a] - fgn[i0a]) * fra;
        const float gnb = fgn[i0b] + (fgn[i1b] - fgn[i0b]) * frb;
        const float bna = fbn[i0a] + (fbn[i1a] - fbn[i0a]) * fra;
        const float bnb = fbn[i0b] + (fbn[i1b] - fbn[i0b]) * frb;

        const float2 e = __ldg(((const float2*)(exciter + (b * NWn + c) * Tn)) + (t0 >> 1) + tid);
        const float isc = sm_isc[c];
        const float x0c = sm_x0[c], hc = sm_h[c], ivh = sm_invh[c];
        const float2* tab = g_tab + c * (TAB_N + 2);

        const float xA = isc * fmaf(gia, e.x, bia);
        const float xB = isc * fmaf(gib, e.y, bib);

        float kfA = floorf((xA - x0c) * ivh);
        kfA = fminf(fmaxf(kfA, 0.0f), (float)(TAB_N - 1));
        const int kA = (int)kfA;
        const float tA_ = (xA - fmaf(kfA, hc, x0c)) * ivh;

        float kfB = floorf((xB - x0c) * ivh);
        kfB = fminf(fmaxf(kfB, 0.0f), (float)(TAB_N - 1));
        const int kB = (int)kfB;
        const float tB_ = (xB - fmaf(kfB, hc, x0c)) * ivh;

        const float2 eA0 = __ldg(tab + kA);
        const float2 eA1 = __ldg(tab + kA + 1);
        const float2 eB0 = __ldg(tab + kB);
        const float2 eB1 = __ldg(tab + kB + 1);

        // cubic Hermite (d pre-scaled by h)
        float c2, c3, y0, y1;
        c2 = 3.0f * (eA1.x - eA0.x) - 2.0f * eA0.y - eA1.y;
        c3 = 2.0f * (eA0.x - eA1.x) + eA0.y + eA1.y;
        y0 = eA0.x + tA_ * (eA0.y + tA_ * (c2 + tA_ * c3));
        c2 = 3.0f * (eB1.x - eB0.x) - 2.0f * eB0.y - eB1.y;
        c3 = 2.0f * (eB0.x - eB1.x) + eB0.y + eB1.y;
        y1 = eB0.x + tB_ * (eB0.y + tB_ * (c2 + tB_ * c3));

        const float mw = sm_mixw[c];
        acc0 += mw * fmaf(gna, y0, bna);
        acc1 += mw * fmaf(gnb, y1, bnb);
    }

    const float mb = __ldg(mixb);
    const float o0 = acc0 + mb;
    const float o1 = acc1 + mb;

    float4* o4 = (float4*)out;
    o4[b * Tn + ta + 0] = make_float4(o0, o0, o0, o0);
    o4[b * Tn + ta + 1] = make_float4(o1, o1, o1, o1);
}

// ---------------------------------------------------------------------------
extern "C" void kernel_launch(void* const* d_in, const int* in_sizes, int n_in,
                              void* d_out, int out_size)
{
    const float* exciter = (const float*)d_in[0];
    const float* cemb    = (const float*)d_in[1];
    const float* mlp_w0  = (const float*)d_in[2];
    const float* mlp_b0  = (const float*)d_in[3];
    const float* ln0_g   = (const float*)d_in[4];
    const float* ln0_b   = (const float*)d_in[5];
    const float* mlp_w1  = (const float*)d_in[6];
    const float* mlp_b1  = (const float*)d_in[7];
    const float* ln1_g   = (const float*)d_in[8];
    const float* ln1_b   = (const float*)d_in[9];
    const float* mlp_w2  = (const float*)d_in[10];
    const float* mlp_b2  = (const float*)d_in[11];
    const float* ln2_g   = (const float*)d_in[12];
    const float* ln2_b   = (const float*)d_in[13];
    const float* mlp_w3  = (const float*)d_in[14];
    const float* mlp_b3  = (const float*)d_in[15];
    const float* iscale  = (const float*)d_in[16];
    const float* sf_w0   = (const float*)d_in[17];
    const float* sf_b0   = (const float*)d_in[18];
    const float* sf_w1   = (const float*)d_in[19];
    const float* sf_b1   = (const float*)d_in[20];
    const float* sf_w2   = (const float*)d_in[21];
    const float* sf_b2   = (const float*)d_in[22];
    const float* mix_w   = (const float*)d_in[23];
    const float* mix_b   = (const float*)d_in[24];
    float* out = (float*)d_out;

    zero_kernel<<<1, 64>>>();
    emax_kernel<<<dim3(NWn, 16), 256>>>(exciter);

    mlp_kernel<<<dim3(TCn / TT, Bn), CEn>>>(cemb,
                            mlp_w0, mlp_b0, ln0_g, ln0_b,
                            mlp_w1, mlp_b1, ln1_g, ln1_b,
                            mlp_w2, mlp_b2, ln2_g, ln2_b,
                            mlp_w3, mlp_b3);

    filmmax_kernel<<<dim3(NWn, 2), 256>>>();

    build_kernel<<<dim3((TAB_N + 1 + 255) / 256, NWn), 256>>>(
        iscale, sf_w0, sf_b0, sf_w1, sf_b1, sf_w2, sf_b2);

    newt_kernel<<<dim3(Tn / 512, Bn), 256>>>(exciter, iscale, mix_w, mix_b, out);
}

// round 12
// speedup vs baseline: 2.9907x; 1.9161x over previous
#include <cuda_runtime.h>
#include <math.h>

#define CEn 128
#define TCn 1024
#define NWn 64
#define Wn  16
#define Tn  65536
#define Bn  4
#define EPSn 1e-5f
#define SLOPEn 0.01f
#define TAB_N 16384

// FiLM params: [B][4*NW][TC] = 4 MB
__device__ float g_film[Bn * 4 * NWn * TCn];
// per-channel range inputs
__device__ unsigned int g_emax_bits[NWn];
__device__ float g_gimax[NWn];
__device__ float g_bimax[NWn];
// waveshaper table, paired nodes: tab4[c][k] = (f_k, h*f'_k, f_{k+1}, h*f'_{k+1})
__device__ float4 g_tab4[NWn * TAB_N];

// ---------------------------------------------------------------------------
__device__ __forceinline__ float blockmax(float v, float* red) {
    const int lane = threadIdx.x & 31, wid = threadIdx.x >> 5;
#pragma unroll
    for (int o = 16; o > 0; o >>= 1)
        v = fmaxf(v, __shfl_xor_sync(0xffffffffu, v, o));
    if (lane == 0) red[wid] = v;
    __syncthreads();
    v = red[0];
#pragma unroll
    for (int w = 1; w < 8; w++) v = fmaxf(v, red[w]);
    return v;
}

__device__ __forceinline__ void get_range(int c, const float* __restrict__ iscale,
                                          float& x0, float& h) {
    const float em = __uint_as_float(g_emax_bits[c]);
    float xm = fabsf(iscale[c]) * (g_gimax[c] * em + g_bimax[c]);
    xm = xm * 1.0005f + 1e-5f;
    x0 = -xm;
    h  = (2.0f * xm) / (float)TAB_N;
}

// ---------------------------------------------------------------------------
__global__ void zero_kernel() {
    if (threadIdx.x < NWn) g_emax_bits[threadIdx.x] = 0u;
}

// max |exciter| per channel. grid (NW, 16), block 256.
__global__ void emax_kernel(const float* __restrict__ exciter) {
    __shared__ float red[8];
    const int c = blockIdx.x, s = blockIdx.y;
    float v = 0.0f;
    for (int b = 0; b < Bn; b++) {
        const float4* p = (const float4*)(exciter + (b * NWn + c) * Tn) + s * 1024;
#pragma unroll 4
        for (int i = threadIdx.x; i < 1024; i += 256) {
            float4 e = __ldg(p + i);
            v = fmaxf(v, fmaxf(fmaxf(fabsf(e.x), fabsf(e.y)),
                               fmaxf(fabsf(e.z), fabsf(e.w))));
        }
    }
    v = blockmax(v, red);
    if (threadIdx.x == 0)
        atomicMax(&g_emax_bits[c], __float_as_uint(v));
}

// max |gamma_i| (part 0) and |beta_i| (part 1) per channel. grid (NW, 2), block 256.
__global__ void filmmax_kernel() {
    __shared__ float red[8];
    const int c = blockIdx.x, p = blockIdx.y;
    float v = 0.0f;
    for (int b = 0; b < Bn; b++) {
        const float4* row = (const float4*)(g_film + (b * 4 * NWn + p * NWn + c) * TCn);
        for (int i = threadIdx.x; i < TCn / 4; i += 256) {
            float4 e = row[i];
            v = fmaxf(v, fmaxf(fmaxf(fabsf(e.x), fabsf(e.y)),
                               fmaxf(fabsf(e.z), fabsf(e.w))));
        }
    }
    v = blockmax(v, red);
    if (threadIdx.x == 0) {
        if (p == 0) g_gimax[c] = v; else g_bimax[c] = v;
    }
}

// ---------------------------------------------------------------------------
// Table build: f_c(x) and analytic derivative at nodes 0..TAB_N; each node
// written into the two float4 entries that reference it.
// grid ((TAB_N+1+255)/256, NW).
// ---------------------------------------------------------------------------
__global__ void __launch_bounds__(256)
build_kernel(const float* __restrict__ iscale,
             const float* __restrict__ sw0, const float* __restrict__ sb0,
             const float* __restrict__ sw1, const float* __restrict__ sb1,
             const float* __restrict__ sw2, const float* __restrict__ sb2)
{
    __shared__ float w0s[Wn], b0s[Wn], w1s[Wn * Wn], b1s[Wn], w2s[Wn];
    __shared__ float b2s;
    const int c = blockIdx.y;
    const int tid = threadIdx.x;
    if (tid < Wn) {
        w0s[tid] = sw0[c * Wn + tid];
        b0s[tid] = sb0[c * Wn + tid];
        b1s[tid] = sb1[c * Wn + tid];
        w2s[tid] = sw2[c * Wn + tid];
        if (tid == 0) b2s = sb2[c];
    }
    if (tid < Wn * Wn) w1s[tid] = sw1[c * Wn * Wn + tid];
    __syncthreads();

    const int k = blockIdx.x * 256 + tid;
    if (k > TAB_N) return;

    float x0, h;
    get_range(c, iscale, x0, h);
    const float x = fmaf((float)k, h, x0);

    float h0[Wn], d0[Wn];
#pragma unroll
    for (int j = 0; j < Wn; j++) {
        float s, cc;
        __sincosf(fmaf(x, w0s[j], b0s[j]), &s, &cc);
        h0[j] = s;
        d0[j] = w0s[j] * cc;
    }
    float h1[Wn], d1[Wn];
#pragma unroll
    for (int o = 0; o < Wn; o++) {
        float a = b1s[o], da = 0.0f;
#pragma unroll
        for (int j = 0; j < Wn; j++) {
            const float w = w1s[o * Wn + j];
            a  = fmaf(w, h0[j], a);
            da = fmaf(w, d0[j], da);
        }
        float s, cc;
        __sincosf(a, &s, &cc);
        h1[o] = s;
        d1[o] = cc * da;
    }
    float a = b2s, da = 0.0f;
#pragma unroll
    for (int o = 0; o < Wn; o++) {
        a  = fmaf(w2s[o], h1[o], a);
        da = fmaf(w2s[o], d1[o], da);
    }
    float s, cc;
    __sincosf(a, &s, &cc);
    const float2 node = make_float2(s, h * cc * da);

    float4* tab = g_tab4 + c * TAB_N;
    if (k < TAB_N)                       // front half of entry k
        *(float2*)&tab[k] = node;
    if (k > 0)                           // back half of entry k-1
        *(float2*)((char*)&tab[k - 1] + 8) = node;
}

// ---------------------------------------------------------------------------
// Kernel 1: TimeDistributedMLP, tiled 16 time-columns per block.
// ---------------------------------------------------------------------------
#define TT 16
__global__ void __launch_bounds__(128)
mlp_kernel(const float* __restrict__ ce,
           const float* __restrict__ w0, const float* __restrict__ b0,
           const float* __restrict__ g0, const float* __restrict__ e0,
           const float* __restrict__ w1, const float* __restrict__ b1,
           const float* __restrict__ g1, const float* __restrict__ e1,
           const float* __restrict__ w2, const float* __restrict__ b2,
           const float* __restrict__ g2, const float* __restrict__ e2,
           const float* __restrict__ w3, const float* __restrict__ b3)
{
    __shared__ float xs[TT][CEn];
    __shared__ float red1[TT][4], red2[TT][4];

    const int t0  = blockIdx.x * TT;
    const int b   = blockIdx.y;
    const int tid = threadIdx.x;
    const int lane = tid & 31;
    const int wid  = tid >> 5;

#pragma unroll
    for (int tt = 0; tt < TT; tt++)
        xs[tt][tid] = ce[(b * CEn + tid) * TCn + t0 + tt];
    __syncthreads();

    const float* Ws[3] = { w0, w1, w2 };
    const float* Bs[3] = { b0, b1, b2 };
    const float* Gs[3] = { g0, g1, g2 };
    const float* Es[3] = { e0, e1, e2 };

    float acc[TT];

    for (int l = 0; l < 3; l++) {
        const float bb = Bs[l][tid];
#pragma unroll
        for (int tt = 0; tt < TT; tt++) acc[tt] = bb;

        const float4* wr = (const float4*)(Ws[l] + tid * CEn);
        for (int i = 0; i < CEn / 4; i++) {
            float4 wv = wr[i];
#pragma unroll
            for (int tt = 0; tt < TT; tt++) {
                const float4 xv = *(const float4*)&xs[tt][4 * i];
                acc[tt] += xv.x * wv.x + xv.y * wv.y + xv.z * wv.z + xv.w * wv.w;
            }
        }

#pragma unroll
        for (int tt = 0; tt < TT; tt++) {
            float s1 = acc[tt], s2 = acc[tt] * acc[tt];
#pragma unroll
            for (int o = 16; o > 0; o >>= 1) {
                s1 += __shfl_xor_sync(0xffffffffu, s1, o);
                s2 += __shfl_xor_sync(0xffffffffu, s2, o);
            }
            if (lane == 0) { red1[tt][wid] = s1; red2[tt][wid] = s2; }
        }
        __syncthreads();

        const float gg = Gs[l][tid], ee = Es[l][tid];
#pragma unroll
        for (int tt = 0; tt < TT; tt++) {
            float s1 = red1[tt][0] + red1[tt][1] + red1[tt][2] + red1[tt][3];
            float s2 = red2[tt][0] + red2[tt][1] + red2[tt][2] + red2[tt][3];
            float mu  = s1 * (1.0f / CEn);
            float var = s2 * (1.0f / CEn) - mu * mu;
            float v = (acc[tt] - mu) * rsqrtf(var + EPSn);
            v = v * gg + ee;
            acc[tt] = (v > 0.0f) ? v : SLOPEn * v;
        }
        __syncthreads();
#pragma unroll
        for (int tt = 0; tt < TT; tt++) xs[tt][tid] = acc[tt];
        __syncthreads();
    }

#pragma unroll
    for (int r = 0; r < 2; r++) {
        const int o = tid + r * CEn;
        const float bb = b3[o];
        float a2[TT];
#pragma unroll
        for (int tt = 0; tt < TT; tt++) a2[tt] = bb;
        const float4* wr = (const float4*)(w3 + o * CEn);
        for (int i = 0; i < CEn / 4; i++) {
            float4 wv = wr[i];
#pragma unroll
            for (int tt = 0; tt < TT; tt++) {
                const float4 xv = *(const float4*)&xs[tt][4 * i];
                a2[tt] += xv.x * wv.x + xv.y * wv.y + xv.z * wv.z + xv.w * wv.w;
            }
        }
#pragma unroll
        for (int tt = 0; tt < TT; tt++)
            g_film[(b * 4 * NWn + o) * TCn + t0 + tt] = a2[tt];
    }
}

// ---------------------------------------------------------------------------
// Kernel 2: table-based waveshaper, single LDG.128 gather per eval.
// 256 threads * 2 samples = 512 samples/block.
// ---------------------------------------------------------------------------
#define NFRAMES 10

__global__ void __launch_bounds__(256)
newt_kernel(const float* __restrict__ exciter,
            const float* __restrict__ iscale,
            const float* __restrict__ mixw, const float* __restrict__ mixb,
            float* __restrict__ out)
{
    __shared__ float smf[4 * NWn * NFRAMES];
    __shared__ float sm_isc[NWn], sm_mixw[NWn];
    __shared__ float sm_x0[NWn], sm_h[NWn], sm_invh[NWn];

    const int tid = threadIdx.x;
    const int b   = blockIdx.y;
    const int t0  = blockIdx.x * 512;
    const int ta  = t0 + 2 * tid;

    if (tid < NWn) {
        sm_isc[tid]  = iscale[tid];
        sm_mixw[tid] = mixw[tid];
        float x0, h;
        get_range(tid, iscale, x0, h);
        sm_x0[tid] = x0; sm_h[tid] = h; sm_invh[tid] = 1.0f / h;
    }

    int base = (int)floorf((t0 + 0.5f) * (1.0f / 64.0f) - 0.5f);
    if (base < 0) base = 0;
    const float* filmB = g_film + b * (4 * NWn * TCn);
    for (int idx = tid; idx < 4 * NWn * NFRAMES; idx += 256) {
        const int p = idx / (NWn * NFRAMES);
        const int rem = idx - p * (NWn * NFRAMES);
        const int c = rem / NFRAMES;
        const int f = rem - c * NFRAMES;
        int fr = base + f; if (fr > TCn - 1) fr = TCn - 1;
        smf[(p * NWn + c) * NFRAMES + f] = filmB[(p * NWn + c) * TCn + fr];
    }
    __syncthreads();

    float pos = (ta + 0.5f) * (1.0f / 64.0f) - 0.5f;
    pos = fminf(fmaxf(pos, 0.0f), (float)(TCn - 1));
    int i0a = (int)pos;
    int i1a = min(i0a + 1, TCn - 1);
    const float fra = pos - (float)i0a;
    i0a -= base; i1a -= base;

    pos = (ta + 1.5f) * (1.0f / 64.0f) - 0.5f;
    pos = fminf(fmaxf(pos, 0.0f), (float)(TCn - 1));
    int i0b = (int)pos;
    int i1b = min(i0b + 1, TCn - 1);
    const float frb = pos - (float)i0b;
    i0b -= base; i1b -= base;

    float acc0 = 0.0f, acc1 = 0.0f;

#pragma unroll 2
    for (int c = 0; c < NWn; c++) {
        const float* fgi = smf + (0 * NWn + c) * NFRAMES;
        const float* fbi = smf + (1 * NWn + c) * NFRAMES;
        const float* fgn = smf + (2 * NWn + c) * NFRAMES;
        const float* fbn = smf + (3 * NWn + c) * NFRAMES;

        const float gia = fgi[i0a] + (fgi[i1a] - fgi[i0a]) * fra;
        const float gib = fgi[i0b] + (fgi[i1b] - fgi[i0b]) * frb;
        const float bia = fbi[i0a] + (fbi[i1a] - fbi[i0a]) * fra;
        const float bib = fbi[i0b] + (fbi[i1b] - fbi[i0b]) * frb;
        const float gna = fgn[i0a] + (fgn[i1a] - fgn[i0a]) * fra;
        const float gnb = fgn[i0b] + (fgn[i1b] - fgn[i0b]) * frb;
        const float bna = fbn[i0a] + (fbn[i1a] - fbn[i0a]) * fra;
        const float bnb = fbn[i0b] + (fbn[i1b] - fbn[i0b]) * frb;

        const float2 e = __ldg(((const float2*)(exciter + (b * NWn + c) * Tn)) + (t0 >> 1) + tid);
        const float isc = sm_isc[c];
        const float x0c = sm_x0[c], hc = sm_h[c], ivh = sm_invh[c];
        const float4* tab = g_tab4 + c * TAB_N;

        const float xA = isc * fmaf(gia, e.x, bia);
        const float xB = isc * fmaf(gib, e.y, bib);

        float kfA = floorf((xA - x0c) * ivh);
        kfA = fminf(fmaxf(kfA, 0.0f), (float)(TAB_N - 1));
        const int kA = (int)kfA;
        const float tA_ = (xA - fmaf(kfA, hc, x0c)) * ivh;

        float kfB = floorf((xB - x0c) * ivh);
        kfB = fminf(fmaxf(kfB, 0.0f), (float)(TAB_N - 1));
        const int kB = (int)kfB;
        const float tB_ = (xB - fmaf(kfB, hc, x0c)) * ivh;

        const float4 eA = __ldg(tab + kA);     // (f0, d0, f1, d1)
        const float4 eB = __ldg(tab + kB);

        // cubic Hermite (d pre-scaled by h)
        float c2, c3, y0, y1;
        c2 = 3.0f * (eA.z - eA.x) - 2.0f * eA.y - eA.w;
        c3 = 2.0f * (eA.x - eA.z) + eA.y + eA.w;
        y0 = eA.x + tA_ * (eA.y + tA_ * (c2 + tA_ * c3));
        c2 = 3.0f * (eB.z - eB.x) - 2.0f * eB.y - eB.w;
        c3 = 2.0f * (eB.x - eB.z) + eB.y + eB.w;
        y1 = eB.x + tB_ * (eB.y + tB_ * (c2 + tB_ * c3));

        const float mw = sm_mixw[c];
        acc0 += mw * fmaf(gna, y0, bna);
        acc1 += mw * fmaf(gnb, y1, bnb);
    }

    const float mb = __ldg(mixb);
    const float o0 = acc0 + mb;
    const float o1 = acc1 + mb;

    float4* o4 = (float4*)out;
    o4[b * Tn + ta + 0] = make_float4(o0, o0, o0, o0);
    o4[b * Tn + ta + 1] = make_float4(o1, o1, o1, o1);
}

// ---------------------------------------------------------------------------
extern "C" void kernel_launch(void* const* d_in, const int* in_sizes, int n_in,
                              void* d_out, int out_size)
{
    const float* exciter = (const float*)d_in[0];
    const float* cemb    = (const float*)d_in[1];
    const float* mlp_w0  = (const float*)d_in[2];
    const float* mlp_b0  = (const float*)d_in[3];
    const float* ln0_g   = (const float*)d_in[4];
    const float* ln0_b   = (const float*)d_in[5];
    const float* mlp_w1  = (const float*)d_in[6];
    const float* mlp_b1  = (const float*)d_in[7];
    const float* ln1_g   = (const float*)d_in[8];
    const float* ln1_b   = (const float*)d_in[9];
    const float* mlp_w2  = (const float*)d_in[10];
    const float* mlp_b2  = (const float*)d_in[11];
    const float* ln2_g   = (const float*)d_in[12];
    const float* ln2_b   = (const float*)d_in[13];
    const float* mlp_w3  = (const float*)d_in[14];
    const float* mlp_b3  = (const float*)d_in[15];
    const float* iscale  = (const float*)d_in[16];
    const float* sf_w0   = (const float*)d_in[17];
    const float* sf_b0   = (const float*)d_in[18];
    const float* sf_w1   = (const float*)d_in[19];
    const float* sf_b1   = (const float*)d_in[20];
    const float* sf_w2   = (const float*)d_in[21];
    const float* sf_b2   = (const float*)d_in[22];
    const float* mix_w   = (const float*)d_in[23];
    const float* mix_b   = (const float*)d_in[24];
    float* out = (float*)d_out;

    zero_kernel<<<1, 64>>>();
    emax_kernel<<<dim3(NWn, 16), 256>>>(exciter);

    mlp_kernel<<<dim3(TCn / TT, Bn), CEn>>>(cemb,
                            mlp_w0, mlp_b0, ln0_g, ln0_b,
                            mlp_w1, mlp_b1, ln1_g, ln1_b,
                            mlp_w2, mlp_b2, ln2_g, ln2_b,
                            mlp_w3, mlp_b3);

    filmmax_kernel<<<dim3(NWn, 2), 256>>>();

    build_kernel<<<dim3((TAB_N + 1 + 255) / 256, NWn), 256>>>(
        iscale, sf_w0, sf_b0, sf_w1, sf_b1, sf_w2, sf_b2);

    newt_kernel<<<dim3(Tn / 512, Bn), 256>>>(exciter, iscale, mix_w, mix_b, out);
}